// round 7
// baseline (speedup 1.0000x reference)
#include <cuda_runtime.h>

#define FULL 0xffffffffu
#define L2E 1.4426950408889634f

typedef unsigned long long u64;

// shared layout offsets (floats), all lane-fastest (conflict-free)
#define L0W 0
#define L0B 256
#define L1Wa 512
#define L1Wb 640
#define L1B 768
#define L2Wa 896
#define L2Wb 960
#define L2B 1024
#define L3Wa 1088
#define L3Wb 1120
#define L3B 1152
#define L4W 1184
#define L4B 1216
#define L5W 1232
#define L5B 1248
#define L6W 1256
#define L6B 1264
#define L7W 1268
#define L7B 1272
#define L8W 1274
#define L8B 1276
#define SC  1280
#define SM_TOT 1288

struct TreeParams {
    const float* w[9];
    const float* b[9];
    const float* alpha;
    const float* beta;
    const float* gamma;
    const float* root_w;
    const float* root_b;
};

__device__ __forceinline__ float ex2f(float x) {
    float y; asm("ex2.approx.ftz.f32 %0, %1;" : "=f"(y) : "f"(x)); return y;
}
__device__ __forceinline__ float rcpf(float x) {
    float y; asm("rcp.approx.ftz.f32 %0, %1;" : "=f"(y) : "f"(x)); return y;
}

// ---- f32x2 packed helpers ----
__device__ __forceinline__ u64 pk(float lo, float hi) {
    u64 r; asm("mov.b64 %0, {%1, %2};" : "=l"(r) : "f"(lo), "f"(hi)); return r;
}
__device__ __forceinline__ void upk(u64 v, float& lo, float& hi) {
    asm("mov.b64 {%0, %1}, %2;" : "=f"(lo), "=f"(hi) : "l"(v));
}
__device__ __forceinline__ u64 fma2(u64 a, u64 b, u64 c) {
    u64 d; asm("fma.rn.f32x2 %0, %1, %2, %3;" : "=l"(d) : "l"(a), "l"(b), "l"(c)); return d;
}
__device__ __forceinline__ u64 add2(u64 a, u64 b) {
    u64 d; asm("add.rn.f32x2 %0, %1, %2;" : "=l"(d) : "l"(a), "l"(b)); return d;
}
__device__ __forceinline__ u64 mul2(u64 a, u64 b) {
    u64 d; asm("mul.rn.f32x2 %0, %1, %2;" : "=l"(d) : "l"(a), "l"(b)); return d;
}
__device__ __forceinline__ u64 bc2(float v) {
    u64 r; asm("mov.b64 %0, {%1, %1};" : "=l"(r) : "f"(v)); return r;
}

// Packed fast 2^t on FMA+ALU pipes (no MUFU). Magic-number split + deg-4 poly.
// rel err ~4e-5, valid |t| < 126 (t3 here stays within ~[-40, 40]).
__device__ __forceinline__ u64 ex2fast2(u64 t) {
    const u64 y  = add2(t, bc2(12582912.0f));
    const u64 ii = add2(y, bc2(-12582912.0f));
    const u64 f  = fma2(bc2(-1.0f), ii, t);
    const u64 p  = fma2(fma2(fma2(fma2(bc2(0.0096181291f), f, bc2(0.0555041087f)),
                       f, bc2(0.2402265069f)), f, bc2(0.6931471806f)), f, bc2(1.0f));
    float ylo, yhi;
    upk(y, ylo, yhi);
    const unsigned slo = (__float_as_uint(ylo) << 23) + 0x3F800000u;
    const unsigned shi = (__float_as_uint(yhi) << 23) + 0x3F800000u;
    return mul2(p, pk(__uint_as_float(slo), __uint_as_float(shi)));
}

struct NckC { u64 cA2, dA2, cB2, dB2, cG2; };

// scalar nck: 3 ex2 + 1 rcp
__device__ __forceinline__ float nck_eval(float z, float cA, float dA,
                                          float cB, float dB, float cG) {
    const float e1 = ex2f(fmaf(-L2E / 8.98f, z, 6.39f * L2E));
    const float e2 = ex2f(fmaf(-L2E / 4.25f, z, -4.4f * L2E));
    const float e3 = ex2f(fmaf(-0.132f * L2E, z, 0.132f * 16.74f * L2E));
    const float a1 = 1.0f + e1;
    const float a2 = 1.0f + e2;
    const float a3 = 0.436f + e3;
    const float d12 = a1 * a2;
    const float R = rcpf(d12 * a3);
    const float n1 = fmaf(cA, z, dA);
    const float n2 = fmaf(cB, z, dB);
    const float q = fmaf(n1, a2, n2 * a1);
    const float num = fmaf(q, a3, cG * d12);
    return num * R;
}

// packed nck: e1,e2 on MUFU, e3 on FMA pipe, 1 rcp/element (6 MUFU per call)
__device__ __forceinline__ u64 nck2p(u64 zz, const NckC& C) {
    const u64 t1 = fma2(bc2(-L2E / 8.98f), zz, bc2(6.39f * L2E));
    const u64 t2 = fma2(bc2(-L2E / 4.25f), zz, bc2(-4.4f * L2E));
    const u64 t3 = fma2(bc2(-0.132f * L2E), zz, bc2(0.132f * 16.74f * L2E));
    float x1a, x1b, x2a, x2b;
    upk(t1, x1a, x1b); upk(t2, x2a, x2b);
    const u64 e1 = pk(ex2f(x1a), ex2f(x1b));
    const u64 e2 = pk(ex2f(x2a), ex2f(x2b));
    const u64 e3 = ex2fast2(t3);
    const u64 a1 = add2(e1, bc2(1.0f));
    const u64 a2 = add2(e2, bc2(1.0f));
    const u64 a3 = add2(e3, bc2(0.436f));
    const u64 d12 = mul2(a1, a2);
    const u64 den = mul2(d12, a3);
    float dla, dlb;
    upk(den, dla, dlb);
    const u64 R = pk(rcpf(dla), rcpf(dlb));
    const u64 n1 = fma2(C.cA2, zz, C.dA2);
    const u64 n2 = fma2(C.cB2, zz, C.dB2);
    const u64 q = fma2(n1, a2, mul2(n2, a1));
    const u64 num = fma2(q, a3, mul2(C.cG2, d12));
    return mul2(num, R);
}

// 8 elements per warp, 128-thread blocks -> 1024 blocks, single-wave residency.
__global__ __launch_bounds__(128) void asym_tree_kernel(
    const float* __restrict__ x, TreeParams P, float* __restrict__ out, int B) {
    __shared__ float sm[SM_TOT];

    const int tid = threadIdx.x;
    const int lane = tid & 31;

    // ---- stage params (block = 128 threads) ----
    for (int i = tid; i < 256; i += 128) {
        const int t = i >> 5, l = i & 31;
        const int r = l * 8 + t;
        sm[L0W + i] = P.w[0][255 - r];
        sm[L0B + i] = P.b[0][510 - r];
    }
    {
        const int s = tid >> 5, l = tid & 31;
        const int k = l * 4 + s;
        sm[L1Wa + tid] = P.w[1][2 * k];
        sm[L1Wb + tid] = P.w[1][2 * k + 1];
        sm[L1B + tid]  = P.b[1][127 + k];
    }
    if (tid < 64) {
        const int s = tid >> 5, l = tid & 31;
        const int k = l * 2 + s;
        sm[L2Wa + tid] = P.w[2][2 * k];
        sm[L2Wb + tid] = P.w[2][2 * k + 1];
        sm[L2B + tid]  = P.b[2][63 + k];
    }
    if (tid < 32) {
        sm[L3Wa + tid] = P.w[3][2 * tid];
        sm[L3Wb + tid] = P.w[3][2 * tid + 1];
        sm[L3B + tid]  = P.b[3][31 + tid];
        sm[L4W + tid]  = P.w[4][tid];
    }
    if (tid < 16) {
        sm[L4B + tid] = P.b[4][15 + tid];
        sm[L5W + tid] = P.w[5][tid];
    }
    if (tid < 8) {
        sm[L5B + tid] = P.b[5][7 + tid];
        sm[L6W + tid] = P.w[6][tid];
    }
    if (tid < 4) {
        sm[L6B + tid] = P.b[6][3 + tid];
        sm[L7W + tid] = P.w[7][tid];
    }
    if (tid < 2) {
        sm[L7B + tid] = P.b[7][1 + tid];
        sm[L8W + tid] = P.w[8][tid];
    }
    if (tid == 0) {
        sm[L8B] = P.b[8][0];
        sm[SC + 0] = P.alpha[0];  sm[SC + 1] = P.beta[0]; sm[SC + 2] = P.gamma[0];
        sm[SC + 3] = P.root_w[0]; sm[SC + 4] = P.root_b[0];
    }
    __syncthreads();

    const float A = sm[SC], Bt = sm[SC + 1], G = sm[SC + 2];
    const float cA = A * 0.0878f, dA = -A * 0.0878f * 113.68f;
    const float cB = Bt * 0.129f, dB = -Bt * 0.129f * 69.62f;
    const float cG = G * 2.23f;
    NckC C;
    C.cA2 = bc2(cA); C.dA2 = bc2(dA);
    C.cB2 = bc2(cB); C.dB2 = bc2(dB);
    C.cG2 = bc2(cG);

    const int warp = (blockIdx.x * 128 + tid) >> 5;
    const int e0 = warp * 8;
    if (e0 >= B) return;

    // ---- levels 0-3: 4 packed pairs -> c[0..7] = v3 (natural order/lane) ----
    float c[8];
#pragma unroll
    for (int p = 0; p < 4; ++p) {
        const int eA = e0 + 2 * p;
        const float* xeA = x + (size_t)eA * 256;
        const float* xeB = xeA + 256;
        const float4 a4A = reinterpret_cast<const float4*>(xeA)[lane * 2];
        const float4 b4A = reinterpret_cast<const float4*>(xeA)[lane * 2 + 1];
        const float4 a4B = reinterpret_cast<const float4*>(xeB)[lane * 2];
        const float4 b4B = reinterpret_cast<const float4*>(xeB)[lane * 2 + 1];
        const float xvA[8] = {a4A.x, a4A.y, a4A.z, a4A.w, b4A.x, b4A.y, b4A.z, b4A.w};
        const float xvB[8] = {a4B.x, a4B.y, a4B.z, a4B.w, b4B.x, b4B.y, b4B.z, b4B.w};

        u64 t1[4];
#pragma unroll
        for (int s = 0; s < 4; ++s) {
            const u64 z0 = fma2(bc2(sm[L0W + (2 * s) * 32 + lane]),
                                pk(xvA[2 * s], xvB[2 * s]),
                                bc2(sm[L0B + (2 * s) * 32 + lane]));
            const u64 z1 = fma2(bc2(sm[L0W + (2 * s + 1) * 32 + lane]),
                                pk(xvA[2 * s + 1], xvB[2 * s + 1]),
                                bc2(sm[L0B + (2 * s + 1) * 32 + lane]));
            const u64 u0 = nck2p(z0, C);
            const u64 u1 = nck2p(z1, C);
            const u64 zl1 = fma2(bc2(sm[L1Wa + s * 32 + lane]), u0,
                           fma2(bc2(sm[L1Wb + s * 32 + lane]), u1,
                                bc2(sm[L1B + s * 32 + lane])));
            t1[s] = nck2p(zl1, C);
        }

        u64 u[4];
#pragma unroll
        for (int s = 0; s < 4; ++s) {
            float lo, hi;
            upk(t1[3 - s], lo, hi);
            u[s] = pk(__shfl_xor_sync(FULL, lo, 31), __shfl_xor_sync(FULL, hi, 31));
        }

        u64 t2[2];
#pragma unroll
        for (int s = 0; s < 2; ++s) {
            const u64 z = fma2(bc2(sm[L2Wa + s * 32 + lane]), u[2 * s],
                         fma2(bc2(sm[L2Wb + s * 32 + lane]), u[2 * s + 1],
                              bc2(sm[L2B + s * 32 + lane])));
            t2[s] = nck2p(z, C);
        }
        float lo1, hi1, lo0, hi0;
        upk(t2[1], lo1, hi1);
        upk(t2[0], lo0, hi0);
        const u64 r0 = pk(__shfl_xor_sync(FULL, lo1, 31), __shfl_xor_sync(FULL, hi1, 31));
        const u64 r1 = pk(__shfl_xor_sync(FULL, lo0, 31), __shfl_xor_sync(FULL, hi0, 31));

        const u64 z3 = fma2(bc2(sm[L3Wa + lane]), r0,
                      fma2(bc2(sm[L3Wb + lane]), r1, bc2(sm[L3B + lane])));
        const u64 cc = nck2p(z3, C);
        upk(cc, c[2 * p], c[2 * p + 1]);
    }

    // ---- level 4: 2 packed calls cover 8 elems ----
    // v4x: lo = elems 0/1 (lanes 0-15 / 16-31), hi = elems 4/5
    // v4y: lo = elems 2/3,                      hi = elems 6/7
    const bool hiH = lane >= 16;
    const int k4 = lane & 15;
    const int i4a = 31 - 2 * k4;
    const int i4b = 30 - 2 * k4;
    const u64 w4a2 = bc2(sm[L4W + 2 * k4]);
    const u64 w4b2 = bc2(sm[L4W + 2 * k4 + 1]);
    const u64 bb42 = bc2(sm[L4B + k4]);

    float v4x_lo, v4x_hi, v4y_lo, v4y_hi;
    {
        const float aL = hiH ? __shfl_sync(FULL, c[1], i4a) : __shfl_sync(FULL, c[0], i4a);
        const float bL = hiH ? __shfl_sync(FULL, c[1], i4b) : __shfl_sync(FULL, c[0], i4b);
        const float aH = hiH ? __shfl_sync(FULL, c[5], i4a) : __shfl_sync(FULL, c[4], i4a);
        const float bH = hiH ? __shfl_sync(FULL, c[5], i4b) : __shfl_sync(FULL, c[4], i4b);
        const u64 z = fma2(w4a2, pk(aL, aH), fma2(w4b2, pk(bL, bH), bb42));
        upk(nck2p(z, C), v4x_lo, v4x_hi);
    }
    {
        const float aL = hiH ? __shfl_sync(FULL, c[3], i4a) : __shfl_sync(FULL, c[2], i4a);
        const float bL = hiH ? __shfl_sync(FULL, c[3], i4b) : __shfl_sync(FULL, c[2], i4b);
        const float aH = hiH ? __shfl_sync(FULL, c[7], i4a) : __shfl_sync(FULL, c[6], i4a);
        const float bH = hiH ? __shfl_sync(FULL, c[7], i4b) : __shfl_sync(FULL, c[6], i4b);
        const u64 z = fma2(w4a2, pk(aL, aH), fma2(w4b2, pk(bL, bH), bb42));
        upk(nck2p(z, C), v4y_lo, v4y_hi);
    }

    // ---- level 5: 1 packed call; out lane = 8e+k (lo: e=0..3, hi: e=4..7) ----
    float v5_lo, v5_hi;
    {
        const int k5 = lane & 7;
        const int e5 = lane >> 3;                 // 0..3
        const bool useY = e5 >= 2;                // elems 2,3 (or 6,7) come from v4y
        const int sla = ((e5 & 1) << 4) + (15 - 2 * k5);
        const int slb = sla - 1;
        const float axl = __shfl_sync(FULL, v4x_lo, sla);
        const float ayl = __shfl_sync(FULL, v4y_lo, sla);
        const float bxl = __shfl_sync(FULL, v4x_lo, slb);
        const float byl = __shfl_sync(FULL, v4y_lo, slb);
        const float axh = __shfl_sync(FULL, v4x_hi, sla);
        const float ayh = __shfl_sync(FULL, v4y_hi, sla);
        const float bxh = __shfl_sync(FULL, v4x_hi, slb);
        const float byh = __shfl_sync(FULL, v4y_hi, slb);
        const float aL = useY ? ayl : axl;
        const float bL = useY ? byl : bxl;
        const float aH = useY ? ayh : axh;
        const float bH = useY ? byh : bxh;
        const u64 w5a2 = bc2(sm[L5W + 2 * k5]);
        const u64 w5b2 = bc2(sm[L5W + 2 * k5 + 1]);
        const u64 z = fma2(w5a2, pk(aL, aH), fma2(w5b2, pk(bL, bH), bc2(sm[L5B + k5])));
        upk(nck2p(z, C), v5_lo, v5_hi);
    }

    // ---- level 6: scalar, out lane = 4e+k (e=0..7) ----
    float v6;
    {
        const int k6 = lane & 3;
        const int e6 = lane >> 2;                 // 0..7
        const int sl = ((e6 & 3) << 3) + (7 - 2 * k6);
        const float al = __shfl_sync(FULL, v5_lo, sl);
        const float ah = __shfl_sync(FULL, v5_hi, sl);
        const float bl = __shfl_sync(FULL, v5_lo, sl - 1);
        const float bh = __shfl_sync(FULL, v5_hi, sl - 1);
        const float pa = (e6 < 4) ? al : ah;
        const float pb = (e6 < 4) ? bl : bh;
        v6 = nck_eval(fmaf(sm[L6W + 2 * k6], pa,
                     fmaf(sm[L6W + 2 * k6 + 1], pb, sm[L6B + k6])),
                      cA, dA, cB, dB, cG);
    }

    // ---- level 7: scalar, out lane = 2e+k (e=0..7, lanes 0-15) ----
    float v7;
    {
        const int k7 = lane & 1;
        const int e7 = (lane >> 1) & 7;
        const int sl = 4 * e7 + (3 - 2 * k7);
        const float pa = __shfl_sync(FULL, v6, sl);
        const float pb = __shfl_sync(FULL, v6, sl - 1);
        v7 = nck_eval(fmaf(sm[L7W + 2 * k7], pa,
                     fmaf(sm[L7W + 2 * k7 + 1], pb, sm[L7B + k7])),
                      cA, dA, cB, dB, cG);
    }

    // ---- level 8 + root: out lane = e (0..7) ----
    {
        const int e8 = lane & 7;
        const float pa = __shfl_sync(FULL, v7, 2 * e8 + 1);
        const float pb = __shfl_sync(FULL, v7, 2 * e8);
        const float v8 = nck_eval(fmaf(sm[L8W], pa, fmaf(sm[L8W + 1], pb, sm[L8B])),
                                  cA, dA, cB, dB, cG);
        if (lane < 8) {
            const float t = fmaf(v8, sm[SC + 3], sm[SC + 4]);
            out[e0 + lane] = rcpf(1.0f + ex2f(-t * L2E));
        }
    }
}

extern "C" void kernel_launch(void* const* d_in, const int* in_sizes, int n_in,
                              void* d_out, int out_size) {
    const float* x = (const float*)d_in[0];
    TreeParams P;
    if (in_sizes[2] == 511) {
        for (int l = 0; l < 9; ++l) {
            P.w[l] = (const float*)d_in[1 + 2 * l];
            P.b[l] = (const float*)d_in[2 + 2 * l];
        }
    } else {
        for (int l = 0; l < 9; ++l) {
            P.w[l] = (const float*)d_in[1 + l];
            P.b[l] = (const float*)d_in[10 + l];
        }
    }
    P.alpha  = (const float*)d_in[19];
    P.beta   = (const float*)d_in[20];
    P.gamma  = (const float*)d_in[21];
    P.root_w = (const float*)d_in[22];
    P.root_b = (const float*)d_in[23];

    const int B = in_sizes[0] / 256;              // 32768
    const int warps = (B + 7) / 8;                // 8 elements per warp -> 4096
    const int grid = (warps + 3) / 4;             // 4 warps per 128-thread block
    asym_tree_kernel<<<grid, 128>>>(x, P, (float*)d_out, B);
}